// round 3
// baseline (speedup 1.0000x reference)
#include <cuda_runtime.h>

// ---------------------------------------------------------------------------
// VNGNN fused kernel, fp32 with packed f32x2 FMA (Blackwell FFMA2).
//
// Pipeline (all launched per kernel_launch call, graph-capturable):
//   k_init      : zero scratch (ctx, denom, count), cmax = enc(-inf)
//   k_wcat      : Wcat[k][o] = o<128 ? Wk[o][k] : H1_w[o-128][k]   (transposed)
//   k_clusterA  : per cluster: qb = g@Wq.T + attn_bias ; g_trans = tanh(g@Fs_w.T+Fs_b)
//   k_clusterB  : per cluster: gG1 = g_trans@G1_w.T + G1_b + H1_b
//   k_main      : per 128-node tile: [K|A1] = Htile @ Wcat (f32x2 SGEMM),
//                 score = tanh(K+qb[cid])·Ws_w + Ws_b, z1 = sigm(A1+gG1[cid]),
//                 h_merged -> out, score -> scratch, atomicMax cluster max, count++
//   k_prefix    : exclusive scan of counts -> offsets/cursors
//   k_scatter   : counting-sort node indices (and scores) by cluster
//   k_ctx       : per (cluster, chunk): gather e=exp(s-m), ctx += e*h, denom += e
//   k_final     : per cluster: ctx/denom, h_trans=tanh(ctx@W_w.T), z2, g_merged -> out
// ---------------------------------------------------------------------------

#define D 128
#define MAXB 524288
#define MAXC 256
#define TBN 128
#define K2_THREADS 512
#define HS_STRIDE 132
#define SPLIT 8
#define ENC_NEG_INF 0x007FFFFFu

// scratch (device globals; no allocation)
__device__ float    d_gtrans[MAXC * D];
__device__ float    d_qb[MAXC * D];
__device__ float    d_gg1[MAXC * D];
__device__ float    d_wcat[D * 2 * D];     // [k][256]
__device__ float    d_score[MAXB];
__device__ float    d_scs[MAXB];           // scores in cluster-sorted order
__device__ int      d_sidx[MAXB];          // node ids in cluster-sorted order
__device__ unsigned d_cmax[MAXC];
__device__ int      d_count[MAXC];
__device__ int      d_offset[MAXC];
__device__ int      d_cursor[MAXC];
__device__ float    d_ctx[MAXC * D];
__device__ float    d_denom[MAXC];

__device__ __forceinline__ unsigned fenc(float f) {
    unsigned u = __float_as_uint(f);
    return (u & 0x80000000u) ? ~u : (u | 0x80000000u);
}
__device__ __forceinline__ float fdec(unsigned u) {
    return (u & 0x80000000u) ? __uint_as_float(u & 0x7FFFFFFFu)
                             : __uint_as_float(~u);
}
__device__ __forceinline__ unsigned long long ff2(
    unsigned long long a, unsigned long long b, unsigned long long c) {
    unsigned long long d;
    asm("fma.rn.f32x2 %0, %1, %2, %3;" : "=l"(d) : "l"(a), "l"(b), "l"(c));
    return d;
}
__device__ __forceinline__ unsigned long long dup2(float x) {
    unsigned long long d;
    unsigned u = __float_as_uint(x);
    asm("mov.b64 %0, {%1, %1};" : "=l"(d) : "r"(u));
    return d;
}

// ---------------------------------------------------------------------------
__global__ void k_init(int C) {
    int t = blockIdx.x * blockDim.x + threadIdx.x;
    if (t < C * D) d_ctx[t] = 0.0f;
    if (t < C) {
        d_denom[t] = 0.0f;
        d_count[t] = 0;
        d_cmax[t]  = ENC_NEG_INF;
    }
}

__global__ void k_wcat(const float* __restrict__ Wk,
                       const float* __restrict__ H1w) {
    int t = blockIdx.x * blockDim.x + threadIdx.x;  // 0..32767
    if (t >= D * 2 * D) return;
    int k = t >> 8;
    int o = t & 255;
    d_wcat[t] = (o < D) ? Wk[o * D + k] : H1w[(o - D) * D + k];
}

__global__ void k_clusterA(const float* __restrict__ g,
                           const float* __restrict__ Wq,
                           const float* __restrict__ Fsw,
                           const float* __restrict__ Fsb,
                           const float* __restrict__ abias) {
    __shared__ float sg[D];
    int c = blockIdx.x, d = threadIdx.x;
    sg[d] = g[c * D + d];
    __syncthreads();
    const float* wq = Wq + d * D;
    const float* fw = Fsw + d * D;
    float q = 0.0f, f = 0.0f;
    #pragma unroll 8
    for (int j = 0; j < D; j++) {
        q += sg[j] * wq[j];
        f += sg[j] * fw[j];
    }
    d_qb[c * D + d]     = q + abias[d];
    d_gtrans[c * D + d] = tanhf(f + Fsb[d]);
}

__global__ void k_clusterB(const float* __restrict__ G1w,
                           const float* __restrict__ G1b,
                           const float* __restrict__ H1b) {
    __shared__ float sg[D];
    int c = blockIdx.x, d = threadIdx.x;
    sg[d] = d_gtrans[c * D + d];
    __syncthreads();
    const float* w = G1w + d * D;
    float a = 0.0f;
    #pragma unroll 8
    for (int j = 0; j < D; j++) a += sg[j] * w[j];
    d_gg1[c * D + d] = a + G1b[d] + H1b[d];
}

// ---------------------------------------------------------------------------
// Big fused kernel: SGEMM (128 nodes x 256 outs x K=128) + epilogue.
// Threads: 512. Thread tile: 16 nodes (8 f32x2 pairs) x 4 outs.
// Smem: Hs[k][node] (transposed h tile, stride 132) + Ws[k][256] (reused as Out).
// ---------------------------------------------------------------------------
__global__ void __launch_bounds__(K2_THREADS, 1)
k_main(const float* __restrict__ h, const int* __restrict__ cid,
       const float* __restrict__ wsw, const float* __restrict__ wsb,
       float* __restrict__ out, int B) {
    extern __shared__ float sm[];
    float* Hs = sm;                      // [128][HS_STRIDE]
    float* Ws = sm + D * HS_STRIDE;      // [128][256] -> reused as Out[node][256]

    int tid = threadIdx.x;
    int n0  = blockIdx.x * TBN;

    // Load Hs transposed: Hs[k][node_local] = h[n0+node][k]
    const float4* h4 = (const float4*)h;
    #pragma unroll
    for (int it = 0; it < 8; it++) {
        int l  = tid + it * 512;         // 0..4095
        int r  = l >> 5;                 // node_local
        int c4 = l & 31;                 // float4 column
        float4 v = make_float4(0.f, 0.f, 0.f, 0.f);
        if (n0 + r < B) v = h4[(size_t)(n0 + r) * 32 + c4];
        int cb = c4 * 4;
        Hs[(cb + 0) * HS_STRIDE + r] = v.x;
        Hs[(cb + 1) * HS_STRIDE + r] = v.y;
        Hs[(cb + 2) * HS_STRIDE + r] = v.z;
        Hs[(cb + 3) * HS_STRIDE + r] = v.w;
    }
    // Load Wcat (already [k][256]) straight copy
    {
        const float4* w4  = (const float4*)d_wcat;
        float4*       Ws4 = (float4*)Ws;
        #pragma unroll
        for (int it = 0; it < 16; it++) {
            int l = tid + it * 512;      // 0..8191
            Ws4[l] = w4[l];
        }
    }
    __syncthreads();

    int tx = tid & 63;   // outputs tx*4 .. tx*4+3
    int ty = tid >> 6;   // nodes   ty*16 .. ty*16+15

    unsigned long long acc[8][4];
    #pragma unroll
    for (int p = 0; p < 8; p++)
        #pragma unroll
        for (int j = 0; j < 4; j++) acc[p][j] = 0ull;

    for (int k = 0; k < D; k++) {
        const ulonglong2* aP =
            (const ulonglong2*)(Hs + k * HS_STRIDE + ty * 16);
        ulonglong2 A0 = aP[0], A1 = aP[1], A2 = aP[2], A3 = aP[3];
        unsigned long long ar[8] = {A0.x, A0.y, A1.x, A1.y,
                                    A2.x, A2.y, A3.x, A3.y};
        float4 bv = *(const float4*)(Ws + k * 256 + tx * 4);
        unsigned long long bd[4] = {dup2(bv.x), dup2(bv.y),
                                    dup2(bv.z), dup2(bv.w)};
        #pragma unroll
        for (int p = 0; p < 8; p++)
            #pragma unroll
            for (int j = 0; j < 4; j++)
                acc[p][j] = ff2(ar[p], bd[j], acc[p][j]);
    }
    __syncthreads();   // all reads of Ws done

    // Spill accumulators to Out[node][256] (overlays Ws)
    #pragma unroll
    for (int p = 0; p < 8; p++) {
        int n = ty * 16 + 2 * p;
        #pragma unroll
        for (int j = 0; j < 4; j++) {
            unsigned lo, hi;
            asm("mov.b64 {%0, %1}, %2;" : "=r"(lo), "=r"(hi) : "l"(acc[p][j]));
            int o = tx * 4 + j;
            Ws[n * 256 + o]       = __uint_as_float(lo);
            Ws[(n + 1) * 256 + o] = __uint_as_float(hi);
        }
    }
    __syncthreads();

    // Epilogue: each warp handles 8 nodes
    int lane = tid & 31;
    int w    = tid >> 5;
    #pragma unroll 1
    for (int nn = 0; nn < 8; nn++) {
        int nl = w * 8 + nn;
        int n  = n0 + nl;
        if (n < B) {
            int c = cid[n];
            const float* qb = d_qb + c * D;
            const float* gg = d_gg1 + c * D;
            const float* gt = d_gtrans + c * D;
            float sc = 0.0f;
            #pragma unroll
            for (int d4 = 0; d4 < 4; d4++) {
                int d = lane + 32 * d4;
                float kv = Ws[nl * 256 + d] + qb[d];
                sc += tanhf(kv) * wsw[d];
                float a1v = Ws[nl * 256 + 128 + d] + gg[d];
                float z   = 1.0f / (1.0f + __expf(-a1v));
                float hv  = Hs[d * HS_STRIDE + nl];
                out[(size_t)n * D + d] = hv + z * (gt[d] - hv);
            }
            #pragma unroll
            for (int off = 16; off; off >>= 1)
                sc += __shfl_xor_sync(0xffffffffu, sc, off);
            if (lane == 0) {
                sc += wsb[0];
                d_score[n] = sc;
                atomicMax(&d_cmax[c], fenc(sc));
                atomicAdd(&d_count[c], 1);
            }
        }
    }
}

// ---------------------------------------------------------------------------
__global__ void k_prefix(int C) {
    __shared__ int s[MAXC];
    int t = threadIdx.x;
    int v = (t < C) ? d_count[t] : 0;
    s[t] = v;
    __syncthreads();
    #pragma unroll
    for (int off = 1; off < MAXC; off <<= 1) {
        int x = (t >= off) ? s[t - off] : 0;
        __syncthreads();
        s[t] += x;
        __syncthreads();
    }
    if (t < C) {
        int excl = s[t] - v;
        d_offset[t] = excl;
        d_cursor[t] = excl;
    }
}

__global__ void k_scatter(const int* __restrict__ cid, int B) {
    int i = blockIdx.x * blockDim.x + threadIdx.x;
    if (i >= B) return;
    int c   = cid[i];
    int pos = atomicAdd(&d_cursor[c], 1);
    d_sidx[pos] = i;
    d_scs[pos]  = d_score[i];
}

// ctx[c] = sum e_i * h_i over nodes of cluster c (split into SPLIT chunks)
__global__ void k_ctx(const float* __restrict__ h) {
    __shared__ int   sidx[128];
    __shared__ float ssc[128];
    int c   = blockIdx.x / SPLIT;
    int s   = blockIdx.x % SPLIT;
    int tid = threadIdx.x;
    int beg = d_offset[c];
    int cnt = d_count[c];
    int chunk = (cnt + SPLIT - 1) / SPLIT;
    int lo = beg + s * chunk;
    int hi = beg + cnt;
    int hi2 = lo + chunk;
    if (hi2 < hi) hi = hi2;

    unsigned mu = d_cmax[c];
    float m = (mu == ENC_NEG_INF) ? 0.0f : fdec(mu);

    float acc = 0.0f, dsum = 0.0f;
    for (int t0 = lo; t0 < hi; t0 += 128) {
        int nload = hi - t0;
        if (nload > 128) nload = 128;
        if (tid < nload) {
            sidx[tid] = d_sidx[t0 + tid];
            ssc[tid]  = d_scs[t0 + tid];
        }
        __syncthreads();
        #pragma unroll 4
        for (int t = 0; t < nload; t++) {
            float e   = __expf(ssc[t] - m);
            int  node = sidx[t];
            acc  += e * h[(size_t)node * D + tid];
            dsum += e;
        }
        __syncthreads();
    }
    if (lo < hi) {
        atomicAdd(&d_ctx[c * D + tid], acc);
        if (tid == 0) atomicAdd(&d_denom[c], dsum);
    }
}

__global__ void k_final(const float* __restrict__ g,
                        const float* __restrict__ Ww,
                        const float* __restrict__ Wb,
                        const float* __restrict__ H2w,
                        const float* __restrict__ H2b,
                        const float* __restrict__ G2w,
                        const float* __restrict__ G2b,
                        float* __restrict__ out, int B) {
    __shared__ float sc[D], sg[D], sh[D];
    int c = blockIdx.x, d = threadIdx.x;
    float den = fmaxf(d_denom[c], 1e-20f);
    sc[d] = d_ctx[c * D + d] / den;
    sg[d] = g[c * D + d];
    __syncthreads();
    const float* w = Ww + d * D;
    float a = 0.0f;
    #pragma unroll 8
    for (int j = 0; j < D; j++) a += sc[j] * w[j];
    float ht = tanhf(a + Wb[d]);
    sh[d] = ht;
    __syncthreads();
    const float* w2 = H2w + d * D;
    const float* w3 = G2w + d * D;
    float acc2 = H2b[d] + G2b[d];
    #pragma unroll 8
    for (int j = 0; j < D; j++) acc2 += sg[j] * w2[j] + sh[j] * w3[j];
    float z  = 1.0f / (1.0f + __expf(-acc2));
    float gv = sg[d];
    out[(size_t)(B + c) * D + d] = gv + z * (ht - gv);
}

// ---------------------------------------------------------------------------
extern "C" void kernel_launch(void* const* d_in, const int* in_sizes, int n_in,
                              void* d_out, int out_size) {
    const float* h     = (const float*)d_in[0];
    const float* g     = (const float*)d_in[1];
    const int*   cid   = (const int*)d_in[2];
    const float* Wq    = (const float*)d_in[3];
    const float* Wk    = (const float*)d_in[4];
    const float* abias = (const float*)d_in[5];
    const float* Wsw   = (const float*)d_in[6];
    const float* Wsb   = (const float*)d_in[7];
    const float* Ww    = (const float*)d_in[8];
    const float* Wb    = (const float*)d_in[9];
    const float* Fsw   = (const float*)d_in[10];
    const float* Fsb   = (const float*)d_in[11];
    const float* H1w   = (const float*)d_in[12];
    const float* H1b   = (const float*)d_in[13];
    const float* G1w   = (const float*)d_in[14];
    const float* G1b   = (const float*)d_in[15];
    const float* H2w   = (const float*)d_in[16];
    const float* H2b   = (const float*)d_in[17];
    const float* G2w   = (const float*)d_in[18];
    const float* G2b   = (const float*)d_in[19];

    int B = in_sizes[0] / D;
    int C = in_sizes[1] / D;
    float* out = (float*)d_out;

    const int smem_bytes = (D * HS_STRIDE + D * 256) * (int)sizeof(float); // 198656
    cudaFuncSetAttribute(k_main, cudaFuncAttributeMaxDynamicSharedMemorySize,
                         smem_bytes);

    k_init<<<(C * D + 255) / 256, 256>>>(C);
    k_wcat<<<(2 * D * D + 255) / 256, 256>>>(Wk, H1w);
    k_clusterA<<<C, D>>>(g, Wq, Fsw, Fsb, abias);
    k_clusterB<<<C, D>>>(G1w, G1b, H1b);
    k_main<<<(B + TBN - 1) / TBN, K2_THREADS, smem_bytes>>>(h, cid, Wsw, Wsb,
                                                            out, B);
    k_prefix<<<1, MAXC>>>(C);
    k_scatter<<<(B + 255) / 256, 256>>>(cid, B);
    k_ctx<<<C * SPLIT, D>>>(h);
    k_final<<<C, D>>>(g, Ww, Wb, H2w, H2b, G2w, G2b, out, B);
}

// round 5
// speedup vs baseline: 1.2800x; 1.2800x over previous
#include <cuda_runtime.h>
#include <cuda_bf16.h>
#include <cstdint>

// ---------------------------------------------------------------------------
// VNGNN fused. GEMM via mma.sync (HMMA, bf16 split-3 => ~fp32 accuracy).
// (tcgen05 is unavailable: harness PTX target is sm_103, not sm_103a.)
//
//   k_init      : zero scratch (ctx, denom, count), cmax = enc(-inf)
//   k_prep      : split Wcat=[Wk;H1_w] -> bf16 hi/lo padded SMEM image (L2)
//   k_clusterA  : qb = g@Wq.T + bias ; g_trans = tanh(g@Fs_w.T + Fs_b)
//   k_clusterB  : gG1 = g_trans@G1_w.T + G1_b + H1_b
//   k_main      : per 128-node tile:
//                   split h tile -> bf16 hi/lo SMEM
//                   Out[128x256] = Ahi*Bhi + Ahi*Blo + Alo*Bhi  (mma.sync)
//                   epilogue: score/tanh, z1/sigmoid, h_merged -> out,
//                   score scratch, atomicMax cluster max, count++
//   k_prefix / k_scatter : counting sort node ids by cluster
//   k_ctx       : gather pass: e=exp(s-m), ctx += e*h, denom += e
//   k_final     : ctx/denom, h_trans, z2, g_merged -> out
// ---------------------------------------------------------------------------

#define D 128
#define MAXB 524288
#define MAXC 256
#define TBN 128
#define NT 512
#define SPLIT 8
#define ENC_NEG_INF 0x007FFFFFu

#define AS 136                     // bf16 elems per padded row (272 B)
#define ROWB (AS * 2)              // 272
#define OFF_AHI 0
#define OFF_ALO (OFF_AHI + 128 * ROWB)       // 34816
#define OFF_BHI (OFF_ALO + 128 * ROWB)       // 69632
#define OFF_BLO (OFF_BHI + 256 * ROWB)       // 139264
#define SMEM_TOTAL (OFF_BLO + 256 * ROWB)    // 208896
#define OUT_STRIDE 257                        // floats; Out overlays B region

// scratch (device globals; no allocation)
__device__ float    d_gtrans[MAXC * D];
__device__ float    d_qb[MAXC * D];
__device__ float    d_gg1[MAXC * D];
__device__ uint4    d_wb[8704];            // [B_hi | B_lo] padded images
__device__ float    d_score[MAXB];
__device__ float    d_scs[MAXB];
__device__ int      d_sidx[MAXB];
__device__ unsigned d_cmax[MAXC];
__device__ int      d_count[MAXC];
__device__ int      d_offset[MAXC];
__device__ int      d_cursor[MAXC];
__device__ float    d_ctx[MAXC * D];
__device__ float    d_denom[MAXC];

// ---------------------------------------------------------------------------
__device__ __forceinline__ uint32_t smem_u32(const void* p) {
    uint32_t a;
    asm("{ .reg .u64 t; cvta.to.shared.u64 t, %1; cvt.u32.u64 %0, t; }"
        : "=r"(a) : "l"(p));
    return a;
}
__device__ __forceinline__ unsigned fenc(float f) {
    unsigned u = __float_as_uint(f);
    return (u & 0x80000000u) ? ~u : (u | 0x80000000u);
}
__device__ __forceinline__ float fdec(unsigned u) {
    return (u & 0x80000000u) ? __uint_as_float(u & 0x7FFFFFFFu)
                             : __uint_as_float(~u);
}
// split two floats into packed bf16 hi and lo words (elem0 in low half)
__device__ __forceinline__ void split2(float a, float b, uint32_t& hi,
                                       uint32_t& lo) {
    __nv_bfloat16 ah = __float2bfloat16(a), bh = __float2bfloat16(b);
    float ar = a - __bfloat162float(ah), br = b - __bfloat162float(bh);
    __nv_bfloat16 al = __float2bfloat16(ar), bl = __float2bfloat16(br);
    hi = (uint32_t)__bfloat16_as_ushort(ah) |
         ((uint32_t)__bfloat16_as_ushort(bh) << 16);
    lo = (uint32_t)__bfloat16_as_ushort(al) |
         ((uint32_t)__bfloat16_as_ushort(bl) << 16);
}
__device__ __forceinline__ void ldmx4(uint32_t addr, uint32_t r[4]) {
    asm volatile("ldmatrix.sync.aligned.m8n8.x4.shared.b16 {%0,%1,%2,%3}, [%4];"
                 : "=r"(r[0]), "=r"(r[1]), "=r"(r[2]), "=r"(r[3]) : "r"(addr));
}
__device__ __forceinline__ void mma16816(float c[4], const uint32_t a[4],
                                         uint32_t b0, uint32_t b1) {
    asm volatile(
        "mma.sync.aligned.m16n8k16.row.col.f32.bf16.bf16.f32 "
        "{%0,%1,%2,%3}, {%4,%5,%6,%7}, {%8,%9}, {%0,%1,%2,%3};"
        : "+f"(c[0]), "+f"(c[1]), "+f"(c[2]), "+f"(c[3])
        : "r"(a[0]), "r"(a[1]), "r"(a[2]), "r"(a[3]), "r"(b0), "r"(b1));
}

// ---------------------------------------------------------------------------
__global__ void k_init(int C) {
    int t = blockIdx.x * blockDim.x + threadIdx.x;
    if (t < C * D) d_ctx[t] = 0.0f;
    if (t < C) {
        d_denom[t] = 0.0f;
        d_count[t] = 0;
        d_cmax[t]  = ENC_NEG_INF;
    }
}

// Pre-split weights: row o = (o<128 ? Wk[o][*] : H1w[o-128][*]), padded 272B.
__global__ void k_prep(const float* __restrict__ Wk,
                       const float* __restrict__ H1w) {
    int t = blockIdx.x * blockDim.x + threadIdx.x;   // 0..4095
    int o = t >> 4;          // output row 0..255
    int c = t & 15;          // 8-elem k chunk
    const float* src = (o < D) ? (Wk + o * D + c * 8)
                               : (H1w + (o - D) * D + c * 8);
    uint32_t hi[4], lo[4];
    #pragma unroll
    for (int j = 0; j < 4; j++) split2(src[2 * j], src[2 * j + 1], hi[j], lo[j]);
    d_wb[o * 17 + c]        = make_uint4(hi[0], hi[1], hi[2], hi[3]);
    d_wb[4352 + o * 17 + c] = make_uint4(lo[0], lo[1], lo[2], lo[3]);
}

__global__ void k_clusterA(const float* __restrict__ g,
                           const float* __restrict__ Wq,
                           const float* __restrict__ Fsw,
                           const float* __restrict__ Fsb,
                           const float* __restrict__ abias) {
    __shared__ float sg[D];
    int c = blockIdx.x, d = threadIdx.x;
    sg[d] = g[c * D + d];
    __syncthreads();
    const float* wq = Wq + d * D;
    const float* fw = Fsw + d * D;
    float q = 0.0f, f = 0.0f;
    #pragma unroll 8
    for (int j = 0; j < D; j++) {
        q += sg[j] * wq[j];
        f += sg[j] * fw[j];
    }
    d_qb[c * D + d]     = q + abias[d];
    d_gtrans[c * D + d] = tanhf(f + Fsb[d]);
}

__global__ void k_clusterB(const float* __restrict__ G1w,
                           const float* __restrict__ G1b,
                           const float* __restrict__ H1b) {
    __shared__ float sg[D];
    int c = blockIdx.x, d = threadIdx.x;
    sg[d] = d_gtrans[c * D + d];
    __syncthreads();
    const float* w = G1w + d * D;
    float a = 0.0f;
    #pragma unroll 8
    for (int j = 0; j < D; j++) a += sg[j] * w[j];
    d_gg1[c * D + d] = a + G1b[d] + H1b[d];
}

// ---------------------------------------------------------------------------
// Main: HMMA GEMM Out[128x256] = Htile[128x128] @ Wcat^T (split-3) + epilogue
// 16 warps; warp tile 32(m) x 64(n).
// ---------------------------------------------------------------------------
__global__ void __launch_bounds__(NT, 1)
k_main(const float* __restrict__ h, const int* __restrict__ cid,
       const float* __restrict__ wsw, const float* __restrict__ wsb,
       float* __restrict__ out, int B) {
    extern __shared__ char sm[];
    uint32_t sb = smem_u32(sm);
    int tid  = threadIdx.x;
    int wid  = tid >> 5;
    int lane = tid & 31;
    int n0blk = blockIdx.x * TBN;

    // ---- copy pre-split weight images (L2-resident) ----
    {
        uint4* bdst = (uint4*)(sm + OFF_BHI);
        #pragma unroll
        for (int it = 0; it < 17; it++) {
            int i = tid + it * NT;
            bdst[i] = d_wb[i];
        }
    }
    // ---- load h tile, split to bf16 hi/lo ----
    {
        const float4* h4 = (const float4*)h;
        #pragma unroll
        for (int it = 0; it < 4; it++) {
            int t = tid + it * NT;       // 0..2047
            int r = t >> 4;              // node row 0..127
            int c = t & 15;              // 8-elem k chunk
            float4 v0 = make_float4(0.f, 0.f, 0.f, 0.f), v1 = v0;
            if (n0blk + r < B) {
                v0 = h4[(size_t)(n0blk + r) * 32 + c * 2];
                v1 = h4[(size_t)(n0blk + r) * 32 + c * 2 + 1];
            }
            uint32_t hi[4], lo[4];
            split2(v0.x, v0.y, hi[0], lo[0]);
            split2(v0.z, v0.w, hi[1], lo[1]);
            split2(v1.x, v1.y, hi[2], lo[2]);
            split2(v1.z, v1.w, hi[3], lo[3]);
            uint32_t bo = (uint32_t)r * ROWB + (uint32_t)c * 16;
            *(uint4*)(sm + OFF_AHI + bo) = make_uint4(hi[0], hi[1], hi[2], hi[3]);
            *(uint4*)(sm + OFF_ALO + bo) = make_uint4(lo[0], lo[1], lo[2], lo[3]);
        }
    }
    __syncthreads();

    // ---- MMA mainloop ----
    int wy = wid & 3;            // m: 4 tiles of 32
    int wx = wid >> 2;           // n: 4 tiles of 64
    int m0 = wy * 32;
    int nb0 = wx * 64;

    float acc[2][8][4];
    #pragma unroll
    for (int mt = 0; mt < 2; mt++)
        #pragma unroll
        for (int nt = 0; nt < 8; nt++)
            #pragma unroll
            for (int j = 0; j < 4; j++) acc[mt][nt][j] = 0.0f;

    // per-lane ldmatrix offset: row = lane&15, kcol = (lane>>4)*8 bf16
    uint32_t lmo = (uint32_t)(lane & 15) * ROWB + (uint32_t)(lane >> 4) * 16;

    #pragma unroll 1
    for (int p = 0; p < 3; p++) {
        uint32_t abase = sb + ((p == 2) ? OFF_ALO : OFF_AHI)
                       + (uint32_t)m0 * ROWB + lmo;
        uint32_t bbase = sb + ((p == 1) ? OFF_BLO : OFF_BHI)
                       + (uint32_t)nb0 * ROWB + lmo;
        #pragma unroll
        for (int kb = 0; kb < 8; kb++) {
            uint32_t ko = (uint32_t)kb * 32;
            uint32_t A0[4], A1[4], Br[4][4];
            ldmx4(abase + ko, A0);
            ldmx4(abase + 16 * ROWB + ko, A1);
            #pragma unroll
            for (int q = 0; q < 4; q++)
                ldmx4(bbase + (uint32_t)q * 16 * ROWB + ko, Br[q]);
            #pragma unroll
            for (int nt = 0; nt < 8; nt++) {
                int q = nt >> 1, hf = nt & 1;
                mma16816(acc[0][nt], A0, Br[q][hf], Br[q][2 + hf]);
                mma16816(acc[1][nt], A1, Br[q][hf], Br[q][2 + hf]);
            }
        }
    }
    __syncthreads();   // all B reads done before Out overlays it

    // ---- spill acc -> Out[node][256] (overlays B region) ----
    float* OutS = (float*)(sm + OFF_BHI);
    {
        int gid = lane >> 2;
        int cl  = 2 * (lane & 3);
        #pragma unroll
        for (int mt = 0; mt < 2; mt++) {
            int r = m0 + mt * 16 + gid;
            #pragma unroll
            for (int nt = 0; nt < 8; nt++) {
                int c = nb0 + nt * 8 + cl;
                OutS[r * OUT_STRIDE + c]           = acc[mt][nt][0];
                OutS[r * OUT_STRIDE + c + 1]       = acc[mt][nt][1];
                OutS[(r + 8) * OUT_STRIDE + c]     = acc[mt][nt][2];
                OutS[(r + 8) * OUT_STRIDE + c + 1] = acc[mt][nt][3];
            }
        }
    }
    __syncthreads();

    // ---- epilogue: each warp handles 8 nodes ----
    #pragma unroll 1
    for (int nn = 0; nn < 8; nn++) {
        int nl = wid * 8 + nn;
        int n  = n0blk + nl;
        if (n < B) {
            int c = cid[n];
            const float* qb = d_qb + c * D;
            const float* gg = d_gg1 + c * D;
            const float* gt = d_gtrans + c * D;
            float sc = 0.0f;
            #pragma unroll
            for (int d4 = 0; d4 < 4; d4++) {
                int d = lane + 32 * d4;
                float kv = OutS[nl * OUT_STRIDE + d] + qb[d];
                sc += tanhf(kv) * wsw[d];
                float a1v = OutS[nl * OUT_STRIDE + 128 + d] + gg[d];
                float z   = 1.0f / (1.0f + __expf(-a1v));
                uint32_t bo = (uint32_t)nl * ROWB + (uint32_t)d * 2;
                float hv =
                    __bfloat162float(*(__nv_bfloat16*)(sm + OFF_AHI + bo)) +
                    __bfloat162float(*(__nv_bfloat16*)(sm + OFF_ALO + bo));
                out[(size_t)n * D + d] = hv + z * (gt[d] - hv);
            }
            #pragma unroll
            for (int off = 16; off; off >>= 1)
                sc += __shfl_xor_sync(0xffffffffu, sc, off);
            if (lane == 0) {
                sc += wsb[0];
                d_score[n] = sc;
                atomicMax(&d_cmax[c], fenc(sc));
                atomicAdd(&d_count[c], 1);
            }
        }
    }
}

// ---------------------------------------------------------------------------
__global__ void k_prefix(int C) {
    __shared__ int s[MAXC];
    int t = threadIdx.x;
    int v = (t < C) ? d_count[t] : 0;
    s[t] = v;
    __syncthreads();
    #pragma unroll
    for (int off = 1; off < MAXC; off <<= 1) {
        int x = (t >= off) ? s[t - off] : 0;
        __syncthreads();
        s[t] += x;
        __syncthreads();
    }
    if (t < C) {
        int excl = s[t] - v;
        d_offset[t] = excl;
        d_cursor[t] = excl;
    }
}

__global__ void k_scatter(const int* __restrict__ cid, int B) {
    int i = blockIdx.x * blockDim.x + threadIdx.x;
    if (i >= B) return;
    int c   = cid[i];
    int pos = atomicAdd(&d_cursor[c], 1);
    d_sidx[pos] = i;
    d_scs[pos]  = d_score[i];
}

__global__ void k_ctx(const float* __restrict__ h) {
    __shared__ int   sidx[128];
    __shared__ float ssc[128];
    int c   = blockIdx.x / SPLIT;
    int s   = blockIdx.x % SPLIT;
    int tid = threadIdx.x;
    int beg = d_offset[c];
    int cnt = d_count[c];
    int chunk = (cnt + SPLIT - 1) / SPLIT;
    int lo = beg + s * chunk;
    int hi = beg + cnt;
    int hi2 = lo + chunk;
    if (hi2 < hi) hi = hi2;

    unsigned mu = d_cmax[c];
    float m = (mu == ENC_NEG_INF) ? 0.0f : fdec(mu);

    float acc = 0.0f, dsum = 0.0f;
    for (int t0 = lo; t0 < hi; t0 += 128) {
        int nload = hi - t0;
        if (nload > 128) nload = 128;
        if (tid < nload) {
            sidx[tid] = d_sidx[t0 + tid];
            ssc[tid]  = d_scs[t0 + tid];
        }
        __syncthreads();
        #pragma unroll 4
        for (int t = 0; t < nload; t++) {
            float e   = __expf(ssc[t] - m);
            int  node = sidx[t];
            acc  += e * h[(size_t)node * D + tid];
            dsum += e;
        }
        __syncthreads();
    }
    if (lo < hi) {
        atomicAdd(&d_ctx[c * D + tid], acc);
        if (tid == 0) atomicAdd(&d_denom[c], dsum);
    }
}

__global__ void k_final(const float* __restrict__ g,
                        const float* __restrict__ Ww,
                        const float* __restrict__ Wb,
                        const float* __restrict__ H2w,
                        const float* __restrict__ H2b,
                        const float* __restrict__ G2w,
                        const float* __restrict__ G2b,
                        float* __restrict__ out, int B) {
    __shared__ float sc[D], sg[D], sh[D];
    int c = blockIdx.x, d = threadIdx.x;
    float den = fmaxf(d_denom[c], 1e-20f);
    sc[d] = d_ctx[c * D + d] / den;
    sg[d] = g[c * D + d];
    __syncthreads();
    const float* w = Ww + d * D;
    float a = 0.0f;
    #pragma unroll 8
    for (int j = 0; j < D; j++) a += sc[j] * w[j];
    float ht = tanhf(a + Wb[d]);
    sh[d] = ht;
    __syncthreads();
    const float* w2 = H2w + d * D;
    const float* w3 = G2w + d * D;
    float acc2 = H2b[d] + G2b[d];
    #pragma unroll 8
    for (int j = 0; j < D; j++) acc2 += sg[j] * w2[j] + sh[j] * w3[j];
    float z  = 1.0f / (1.0f + __expf(-acc2));
    float gv = sg[d];
    out[(size_t)(B + c) * D + d] = gv + z * (ht - gv);
}

// ---------------------------------------------------------------------------
extern "C" void kernel_launch(void* const* d_in, const int* in_sizes, int n_in,
                              void* d_out, int out_size) {
    const float* h     = (const float*)d_in[0];
    const float* g     = (const float*)d_in[1];
    const int*   cid   = (const int*)d_in[2];
    const float* Wq    = (const float*)d_in[3];
    const float* Wk    = (const float*)d_in[4];
    const float* abias = (const float*)d_in[5];
    const float* Wsw   = (const float*)d_in[6];
    const float* Wsb   = (const float*)d_in[7];
    const float* Ww    = (const float*)d_in[8];
    const float* Wb    = (const float*)d_in[9];
    const float* Fsw   = (const float*)d_in[10];
    const float* Fsb   = (const float*)d_in[11];
    const float* H1w   = (const float*)d_in[12];
    const float* H1b   = (const float*)d_in[13];
    const float* G1w   = (const float*)d_in[14];
    const float* G1b   = (const float*)d_in[15];
    const float* H2w   = (const float*)d_in[16];
    const float* H2b   = (const float*)d_in[17];
    const float* G2w   = (const float*)d_in[18];
    const float* G2b   = (const float*)d_in[19];

    int B = in_sizes[0] / D;
    int C = in_sizes[1] / D;
    float* out = (float*)d_out;

    cudaFuncSetAttribute(k_main, cudaFuncAttributeMaxDynamicSharedMemorySize,
                         SMEM_TOTAL);

    k_init<<<(C * D + 255) / 256, 256>>>(C);
    k_prep<<<16, 256>>>(Wk, H1w);
    k_clusterA<<<C, D>>>(g, Wq, Fsw, Fsb, abias);
    k_clusterB<<<C, D>>>(G1w, G1b, H1b);
    k_main<<<(B + TBN - 1) / TBN, NT, SMEM_TOTAL>>>(h, cid, Wsw, Wsb, out, B);
    k_prefix<<<1, MAXC>>>(C);
    k_scatter<<<(B + 255) / 256, 256>>>(cid, B);
    k_ctx<<<C * SPLIT, D>>>(h);
    k_final<<<C, D>>>(g, Ww, Wb, H2w, H2b, G2w, G2b, out, B);
}